// round 1
// baseline (speedup 1.0000x reference)
#include <cuda_runtime.h>
#include <float.h>
#include <math.h>

#define N_PROT 50000
#define N_SUB  2000
#define D      256     // D_PROT == D_SUB
#define DP     128     // D_PROJ
#define KERN   16
#define N_INT  64
#define NW     (N_PROT - KERN + 1)   // 49985

#define NB_PROT 6250      // 6250*8 = 50000 rows
#define NB_SUB  250       // 250*8  = 2000 rows
#define NB_K1   (NB_PROT + NB_SUB + 1)
#define NB_WIN  196       // 196*256 = 50176 >= NW

// -------- device scratch (no allocations allowed) --------
__device__ float d_g[N_PROT];
__device__ float d_s[N_PROT];
__device__ float d_v[D];
__device__ float d_u[D];
__device__ float d_reaction[DP];
__device__ float d_cg;
__device__ float d_cs;
__device__ float d_blkVal[NB_WIN];
__device__ int   d_blkIdx[NB_WIN];
__device__ int   d_top;

// ============================================================
// k0: reaction = (sum of selected sub rows) @ Ws + 64*bs
//     v = Wp @ w1 ; u = Wp @ ones ; scalar constants
// ============================================================
__global__ void k0_prep(const float* __restrict__ sub_node,
                        const int*   __restrict__ int_index,
                        const float* __restrict__ Wp,
                        const float* __restrict__ bp,
                        const float* __restrict__ Ws,
                        const float* __restrict__ bs,
                        const float* __restrict__ wa,
                        const float* __restrict__ ba)
{
    __shared__ float ssum[D];
    __shared__ float sreact[DP];
    int t = threadIdx.x;   // 256 threads

    // column sum of the 64 selected sub rows
    float acc = 0.f;
    #pragma unroll 4
    for (int m = 0; m < N_INT; m++)
        acc += sub_node[(size_t)int_index[m] * D + t];
    ssum[t] = acc;
    __syncthreads();

    if (t < DP) {
        float r = 0.f;
        #pragma unroll 8
        for (int j = 0; j < D; j++)
            r += ssum[j] * Ws[j * DP + t];
        r += (float)N_INT * bs[t];
        sreact[t]     = r;
        d_reaction[t] = r;
    }

    // v[j] = sum_p Wp[j,p]*w1[p] ; u[j] = sum_p Wp[j,p]
    {
        const float* wrow = Wp + (size_t)t * DP;
        float vv = 0.f, uu = 0.f;
        #pragma unroll 8
        for (int p = 0; p < DP; p++) {
            float w = wrow[p];
            vv += w * wa[p];
            uu += w;
        }
        d_v[t] = vv;
        d_u[t] = uu;
    }
    __syncthreads();

    if (t == 0) {
        float cg = ba[0];
        float cs = 0.f;
        for (int p = 0; p < DP; p++) {
            cg += bp[p] * wa[p];
            cg += sreact[p] * wa[DP + p];
            cs += bp[p];
        }
        d_cg = cg;
        d_cs = cs;
    }
}

// ============================================================
// k1: fused prot copy + g/s matvecs, sub copy, index tail
//     one warp per row; lane loads float4[lane] and float4[lane+32]
// ============================================================
__global__ void k1_main(const float* __restrict__ prot,
                        const float* __restrict__ subn,
                        const int*   __restrict__ idx,
                        float* __restrict__ out)
{
    int b    = blockIdx.x;
    int t    = threadIdx.x;
    int warp = t >> 5;
    int lane = t & 31;

    if (b < NB_PROT) {
        int row = b * 8 + warp;
        const float4* src = (const float4*)(prot + (size_t)row * D);
        float4*       dst = (float4*)(out + (size_t)row * D);
        const float4* v4  = (const float4*)d_v;
        const float4* u4  = (const float4*)d_u;

        float4 a = src[lane];
        float4 c = src[lane + 32];
        dst[lane]      = a;
        dst[lane + 32] = c;

        float4 va = v4[lane], vc = v4[lane + 32];
        float4 ua = u4[lane], uc = u4[lane + 32];

        float gv = a.x*va.x + a.y*va.y + a.z*va.z + a.w*va.w
                 + c.x*vc.x + c.y*vc.y + c.z*vc.z + c.w*vc.w;
        float sv = a.x*ua.x + a.y*ua.y + a.z*ua.z + a.w*ua.w
                 + c.x*uc.x + c.y*uc.y + c.z*uc.z + c.w*uc.w;

        #pragma unroll
        for (int o = 16; o > 0; o >>= 1) {
            gv += __shfl_down_sync(0xffffffffu, gv, o);
            sv += __shfl_down_sync(0xffffffffu, sv, o);
        }
        if (lane == 0) {
            d_g[row] = gv + d_cg;
            d_s[row] = sv + d_cs;
        }
    } else if (b < NB_PROT + NB_SUB) {
        int row = (b - NB_PROT) * 8 + warp;
        const float4* src = (const float4*)(subn + (size_t)row * D);
        float4*       dst = (float4*)(out + (size_t)(N_PROT + row) * D);
        dst[lane]      = src[lane];
        dst[lane + 32] = src[lane + 32];
    } else {
        if (t < N_INT)
            out[(size_t)(N_PROT + N_SUB) * D + t] = (float)idx[t];
    }
}

// ============================================================
// k2a: per-window softmax-weighted score, per-block argmax
// ============================================================
__global__ void k2a_window(void)
{
    __shared__ float sg[256 + KERN];
    __shared__ float ss[256 + KERN];
    __shared__ float bval[256];
    __shared__ int   bidx[256];

    int b    = blockIdx.x;
    int t    = threadIdx.x;
    int base = b * 256;

    for (int i = t; i < 256 + KERN - 1; i += 256) {
        int gi = base + i;
        sg[i] = (gi < N_PROT) ? d_g[gi] : -FLT_MAX;
        ss[i] = (gi < N_PROT) ? d_s[gi] : 0.f;
    }
    __syncthreads();

    int   w = base + t;
    float A = -FLT_MAX;
    if (w < NW) {
        float m = sg[t];
        #pragma unroll
        for (int k = 1; k < KERN; k++) m = fmaxf(m, sg[t + k]);
        float wsum = 0.f, asum = 0.f;
        #pragma unroll
        for (int k = 0; k < KERN; k++) {
            float e = expf(sg[t + k] - m);
            wsum += e;
            asum += e * ss[t + k];
        }
        A = asum / wsum;
    }
    bval[t] = A;
    bidx[t] = w;
    __syncthreads();

    for (int off = 128; off > 0; off >>= 1) {
        if (t < off) {
            float ov = bval[t + off];
            int   oi = bidx[t + off];
            if (ov > bval[t] || (ov == bval[t] && oi < bidx[t])) {
                bval[t] = ov;
                bidx[t] = oi;
            }
        }
        __syncthreads();
    }
    if (t == 0) {
        d_blkVal[b] = bval[0];
        d_blkIdx[b] = bidx[0];
    }
}

// ============================================================
// k2b: reduce per-block results -> d_top (first-index tie-break)
// ============================================================
__global__ void k2b_reduce(void)
{
    __shared__ float bval[256];
    __shared__ int   bidx[256];
    int t = threadIdx.x;

    if (t < NB_WIN) { bval[t] = d_blkVal[t]; bidx[t] = d_blkIdx[t]; }
    else            { bval[t] = -FLT_MAX;    bidx[t] = 0x7fffffff; }
    __syncthreads();

    for (int off = 128; off > 0; off >>= 1) {
        if (t < off) {
            float ov = bval[t + off];
            int   oi = bidx[t + off];
            if (ov > bval[t] || (ov == bval[t] && oi < bidx[t])) {
                bval[t] = ov;
                bidx[t] = oi;
            }
        }
        __syncthreads();
    }
    if (t == 0) d_top = bidx[0];
}

// ============================================================
// k3: finalize — project the 16 winning rows, attn, top_score,
//     deltas, patch 16 prot rows and 64 sub rows of out.
// ============================================================
__global__ void k3_final(const float* __restrict__ prot,
                         const float* __restrict__ subn,
                         const int*   __restrict__ idx,
                         const float* __restrict__ Wp,
                         const float* __restrict__ bp,
                         const float* __restrict__ sub_out,
                         const float* __restrict__ prot_out,
                         float* __restrict__ out)
{
    __shared__ float pp[KERN][DP];    // prot_proj for the 16 rows
    __shared__ float attn[KERN];
    __shared__ float ts[DP];          // top_score
    __shared__ float dprot[D];
    __shared__ float dsub[D];

    int t   = threadIdx.x;            // 256 threads
    int top = d_top;

    // prot_proj rows top..top+15  (2048 dot products of length 256)
    for (int e = t; e < KERN * DP; e += 256) {
        int k = e >> 7;       // e / 128
        int d = e & (DP - 1);
        const float* row = prot + (size_t)(top + k) * D;
        float acc = bp[d];
        #pragma unroll 8
        for (int j = 0; j < D; j++)
            acc += row[j] * Wp[j * DP + d];
        pp[k][d] = acc;
    }
    __syncthreads();

    if (t == 0) {
        float m = d_g[top];
        for (int k = 1; k < KERN; k++) m = fmaxf(m, d_g[top + k]);
        float wsum = 0.f;
        float e[KERN];
        for (int k = 0; k < KERN; k++) {
            e[k] = expf(d_g[top + k] - m);
            wsum += e[k];
        }
        for (int k = 0; k < KERN; k++) attn[k] = e[k] / wsum;
    }
    __syncthreads();

    if (t < DP) {
        float acc = d_reaction[t];
        #pragma unroll
        for (int k = 0; k < KERN; k++) acc += attn[k] * pp[k][t];
        ts[t] = acc;
    }
    __syncthreads();

    // deltas: prot_out / sub_out are (128, 256) row-major
    {
        float dp_ = 0.f, ds_ = 0.f;
        #pragma unroll 8
        for (int d = 0; d < DP; d++) {
            float s = ts[d];
            dp_ += s * prot_out[d * D + t];
            ds_ += s * sub_out[d * D + t];
        }
        dprot[t] = dp_;
        dsub[t]  = ds_;
    }
    __syncthreads();

    // patch prot rows (out already holds the copy)
    #pragma unroll
    for (int k = 0; k < KERN; k++)
        out[(size_t)(top + k) * D + t] += dprot[t];

    // patch sub rows (set semantics: same value for duplicate indices)
    for (int m = 0; m < N_INT; m++) {
        int r = idx[m];
        out[(size_t)(N_PROT + r) * D + t] = subn[(size_t)r * D + t] + dsub[t];
    }
}

// ============================================================
extern "C" void kernel_launch(void* const* d_in, const int* in_sizes, int n_in,
                              void* d_out, int out_size)
{
    const float* prot_node = (const float*)d_in[0];
    const float* sub_node  = (const float*)d_in[1];
    const int*   int_index = (const int*)  d_in[2];
    const float* Wp        = (const float*)d_in[3];
    const float* bp        = (const float*)d_in[4];
    const float* Ws        = (const float*)d_in[5];
    const float* bs        = (const float*)d_in[6];
    const float* wa        = (const float*)d_in[7];
    const float* ba        = (const float*)d_in[8];
    const float* sub_out   = (const float*)d_in[9];
    const float* prot_out  = (const float*)d_in[10];
    float*       out       = (float*)d_out;

    k0_prep<<<1, 256>>>(sub_node, int_index, Wp, bp, Ws, bs, wa, ba);
    k1_main<<<NB_K1, 256>>>(prot_node, sub_node, int_index, out);
    k2a_window<<<NB_WIN, 256>>>();
    k2b_reduce<<<1, 256>>>();
    k3_final<<<1, 256>>>(prot_node, sub_node, int_index, Wp, bp,
                         sub_out, prot_out, out);
}

// round 2
// speedup vs baseline: 1.8701x; 1.8701x over previous
#include <cuda_runtime.h>
#include <float.h>
#include <math.h>

#define N_PROT 50000
#define N_SUB  2000
#define D      256     // D_PROT == D_SUB
#define DP     128     // D_PROJ
#define KERN   16
#define N_INT  64
#define NW     (N_PROT - KERN + 1)   // 49985

#define NB_PROT 6250      // 6250*8 = 50000 rows
#define NB_SUB  250       // 250*8  = 2000 rows
#define NB_K1   (NB_PROT + NB_SUB + 1)
#define NB_WIN  196       // 196*256 = 50176 >= NW

// -------- device scratch (no allocations allowed) --------
__device__ float d_g[N_PROT];
__device__ float d_s[N_PROT];
__device__ float d_v[D];
__device__ float d_u[D];
__device__ float d_reaction[DP];
__device__ float d_cg;
__device__ float d_cs;
__device__ float d_blkVal[NB_WIN];
__device__ int   d_blkIdx[NB_WIN];

// ============================================================
// k0: reaction = (sum of selected sub rows) @ Ws + 64*bs
//     v = Wp @ w1 ; u = Wp @ ones ; cg/cs via parallel reduction
// ============================================================
__global__ void k0_prep(const float* __restrict__ sub_node,
                        const int*   __restrict__ int_index,
                        const float* __restrict__ Wp,
                        const float* __restrict__ bp,
                        const float* __restrict__ Ws,
                        const float* __restrict__ bs,
                        const float* __restrict__ wa,
                        const float* __restrict__ ba)
{
    __shared__ float ssum[D];
    __shared__ float sreact[DP];
    __shared__ float red[8];
    int t    = threadIdx.x;   // 256 threads
    int lane = t & 31;
    int warp = t >> 5;

    // column sum of the 64 selected sub rows (idx loads are broadcast)
    float acc = 0.f;
    #pragma unroll 8
    for (int m = 0; m < N_INT; m++)
        acc += sub_node[(size_t)int_index[m] * D + t];
    ssum[t] = acc;

    // v[j] = sum_p Wp[j,p]*w1[p] ; u[j] = sum_p Wp[j,p]  (independent of ssum)
    {
        const float* wrow = Wp + (size_t)t * DP;
        float vv = 0.f, uu = 0.f;
        #pragma unroll 16
        for (int p = 0; p < DP; p++) {
            float w = wrow[p];
            vv += w * wa[p];
            uu += w;
        }
        d_v[t] = vv;
        d_u[t] = uu;
    }
    __syncthreads();

    if (t < DP) {
        float r = 0.f;
        #pragma unroll 16
        for (int j = 0; j < D; j++)
            r += ssum[j] * Ws[j * DP + t];
        r += (float)N_INT * bs[t];
        sreact[t]     = r;
        d_reaction[t] = r;
    }
    __syncthreads();

    // cg = ba + sum_p ( bp[p]*wa[p] + react[p]*wa[128+p] ) ; cs = sum_p bp[p]
    float p1 = 0.f, p2 = 0.f;
    if (t < DP) {
        float b = bp[t];
        p1 = b * wa[t] + sreact[t] * wa[DP + t];
        p2 = b;
    }
    #pragma unroll
    for (int o = 16; o > 0; o >>= 1) {
        p1 += __shfl_xor_sync(0xffffffffu, p1, o);
        p2 += __shfl_xor_sync(0xffffffffu, p2, o);
    }
    if (lane == 0 && warp < 4) { red[warp] = p1; red[4 + warp] = p2; }
    __syncthreads();
    if (t == 0) {
        d_cg = ba[0] + red[0] + red[1] + red[2] + red[3];
        d_cs = red[4] + red[5] + red[6] + red[7];
    }
}

// ============================================================
// k1: fused prot copy + g/s matvecs, sub copy, index tail
//     one warp per row; lane loads float4[lane] and float4[lane+32]
// ============================================================
__global__ void k1_main(const float* __restrict__ prot,
                        const float* __restrict__ subn,
                        const int*   __restrict__ idx,
                        float* __restrict__ out)
{
    int b    = blockIdx.x;
    int t    = threadIdx.x;
    int warp = t >> 5;
    int lane = t & 31;

    if (b < NB_PROT) {
        int row = b * 8 + warp;
        const float4* src = (const float4*)(prot + (size_t)row * D);
        float4*       dst = (float4*)(out + (size_t)row * D);
        const float4* v4  = (const float4*)d_v;
        const float4* u4  = (const float4*)d_u;

        float4 a = src[lane];
        float4 c = src[lane + 32];
        dst[lane]      = a;
        dst[lane + 32] = c;

        float4 va = v4[lane], vc = v4[lane + 32];
        float4 ua = u4[lane], uc = u4[lane + 32];

        float gv = a.x*va.x + a.y*va.y + a.z*va.z + a.w*va.w
                 + c.x*vc.x + c.y*vc.y + c.z*vc.z + c.w*vc.w;
        float sv = a.x*ua.x + a.y*ua.y + a.z*ua.z + a.w*ua.w
                 + c.x*uc.x + c.y*uc.y + c.z*uc.z + c.w*uc.w;

        #pragma unroll
        for (int o = 16; o > 0; o >>= 1) {
            gv += __shfl_down_sync(0xffffffffu, gv, o);
            sv += __shfl_down_sync(0xffffffffu, sv, o);
        }
        if (lane == 0) {
            d_g[row] = gv + d_cg;
            d_s[row] = sv + d_cs;
        }
    } else if (b < NB_PROT + NB_SUB) {
        int row = (b - NB_PROT) * 8 + warp;
        const float4* src = (const float4*)(subn + (size_t)row * D);
        float4*       dst = (float4*)(out + (size_t)(N_PROT + row) * D);
        dst[lane]      = src[lane];
        dst[lane + 32] = src[lane + 32];
    } else {
        if (t < N_INT)
            out[(size_t)(N_PROT + N_SUB) * D + t] = (float)idx[t];
    }
}

// ============================================================
// k2a: per-window softmax-weighted score, per-block argmax
// ============================================================
__global__ void k2a_window(void)
{
    __shared__ float sg[256 + KERN];
    __shared__ float ss[256 + KERN];
    __shared__ float bval[256];
    __shared__ int   bidx[256];

    int b    = blockIdx.x;
    int t    = threadIdx.x;
    int base = b * 256;

    for (int i = t; i < 256 + KERN - 1; i += 256) {
        int gi = base + i;
        sg[i] = (gi < N_PROT) ? d_g[gi] : -FLT_MAX;
        ss[i] = (gi < N_PROT) ? d_s[gi] : 0.f;
    }
    __syncthreads();

    int   w = base + t;
    float A = -FLT_MAX;
    if (w < NW) {
        float m = sg[t];
        #pragma unroll
        for (int k = 1; k < KERN; k++) m = fmaxf(m, sg[t + k]);
        float wsum = 0.f, asum = 0.f;
        #pragma unroll
        for (int k = 0; k < KERN; k++) {
            float e = expf(sg[t + k] - m);
            wsum += e;
            asum += e * ss[t + k];
        }
        A = asum / wsum;
    }
    bval[t] = A;
    bidx[t] = w;
    __syncthreads();

    for (int off = 128; off > 0; off >>= 1) {
        if (t < off) {
            float ov = bval[t + off];
            int   oi = bidx[t + off];
            if (ov > bval[t] || (ov == bval[t] && oi < bidx[t])) {
                bval[t] = ov;
                bidx[t] = oi;
            }
        }
        __syncthreads();
    }
    if (t == 0) {
        d_blkVal[b] = bval[0];
        d_blkIdx[b] = bidx[0];
    }
}

// ============================================================
// k3: final reduce (merged k2b) + finalize @ 1024 threads
// ============================================================
__global__ void __launch_bounds__(1024)
k3_final(const float* __restrict__ prot,
         const float* __restrict__ subn,
         const int*   __restrict__ idx,
         const float* __restrict__ Wp,
         const float* __restrict__ bp,
         const float* __restrict__ sub_out,
         const float* __restrict__ prot_out,
         float* __restrict__ out)
{
    __shared__ float bval[256];
    __shared__ int   bidx[256];
    __shared__ int   s_top;
    __shared__ float srows[KERN][D];  // 16 winning prot rows  (16 KB)
    __shared__ float pp[KERN][DP];    // prot_proj of those rows (8 KB)
    __shared__ float attn[KERN];
    __shared__ float ts[DP];          // top_score
    __shared__ float dprot[D];
    __shared__ float dsub[D];

    int t = threadIdx.x;              // 1024 threads

    // ---- merged k2b: reduce 196 block candidates -> top ----
    if (t < 256) {
        if (t < NB_WIN) { bval[t] = d_blkVal[t]; bidx[t] = d_blkIdx[t]; }
        else            { bval[t] = -FLT_MAX;    bidx[t] = 0x7fffffff; }
    }
    __syncthreads();
    for (int off = 128; off > 0; off >>= 1) {
        if (t < off) {
            float ov = bval[t + off];
            int   oi = bidx[t + off];
            if (ov > bval[t] || (ov == bval[t] && oi < bidx[t])) {
                bval[t] = ov;
                bidx[t] = oi;
            }
        }
        __syncthreads();
    }
    if (t == 0) s_top = bidx[0];
    __syncthreads();
    int top = s_top;

    // ---- stage the 16 winning rows into shared (coalesced) ----
    #pragma unroll
    for (int e = t; e < KERN * D; e += 1024)
        ((float*)srows)[e] = prot[(size_t)top * D + e];

    // ---- attn (one warp) ----
    if (t < 32) {
        float gk = (t < KERN) ? d_g[top + t] : -FLT_MAX;
        float m = gk;
        #pragma unroll
        for (int o = 16; o > 0; o >>= 1)
            m = fmaxf(m, __shfl_xor_sync(0xffffffffu, m, o));
        float e = (t < KERN) ? expf(gk - m) : 0.f;
        float sum = e;
        #pragma unroll
        for (int o = 16; o > 0; o >>= 1)
            sum += __shfl_xor_sync(0xffffffffu, sum, o);
        if (t < KERN) attn[t] = e / sum;
    }
    __syncthreads();

    // ---- prot_proj: 2048 dots, 2 per thread, Wp coalesced ----
    #pragma unroll
    for (int ee = 0; ee < 2; ee++) {
        int e = t + ee * 1024;
        int k = e >> 7;               // / 128
        int d = e & (DP - 1);
        float acc = bp[d];
        const float* row = srows[k];
        #pragma unroll 16
        for (int j = 0; j < D; j++)
            acc += row[j] * Wp[j * DP + d];
        pp[k][d] = acc;
    }
    __syncthreads();

    // ---- top_score ----
    if (t < DP) {
        float acc = d_reaction[t];
        #pragma unroll
        for (int k = 0; k < KERN; k++) acc += attn[k] * pp[k][t];
        ts[t] = acc;
    }
    __syncthreads();

    // ---- deltas: prot_out / sub_out are (128, 256) row-major ----
    if (t < 256) {
        float a = 0.f;
        #pragma unroll 16
        for (int d = 0; d < DP; d++)
            a += ts[d] * prot_out[d * D + t];
        dprot[t] = a;
    } else if (t < 512) {
        int c = t - 256;
        float a = 0.f;
        #pragma unroll 16
        for (int d = 0; d < DP; d++)
            a += ts[d] * sub_out[d * D + c];
        dsub[c] = a;
    }
    __syncthreads();

    // ---- patch prot rows (out already holds the copy) ----
    #pragma unroll
    for (int e = t; e < KERN * D; e += 1024) {
        int c = e & (D - 1);
        out[(size_t)top * D + e] += dprot[c];
    }

    // ---- patch sub rows (set semantics; duplicates write same value) ----
    #pragma unroll
    for (int e = t; e < N_INT * D; e += 1024) {
        int m = e >> 8;
        int c = e & (D - 1);
        int r = idx[m];
        out[(size_t)(N_PROT + r) * D + c] = subn[(size_t)r * D + c] + dsub[c];
    }
}

// ============================================================
extern "C" void kernel_launch(void* const* d_in, const int* in_sizes, int n_in,
                              void* d_out, int out_size)
{
    const float* prot_node = (const float*)d_in[0];
    const float* sub_node  = (const float*)d_in[1];
    const int*   int_index = (const int*)  d_in[2];
    const float* Wp        = (const float*)d_in[3];
    const float* bp        = (const float*)d_in[4];
    const float* Ws        = (const float*)d_in[5];
    const float* bs        = (const float*)d_in[6];
    const float* wa        = (const float*)d_in[7];
    const float* ba        = (const float*)d_in[8];
    const float* sub_out   = (const float*)d_in[9];
    const float* prot_out  = (const float*)d_in[10];
    float*       out       = (float*)d_out;

    k0_prep<<<1, 256>>>(sub_node, int_index, Wp, bp, Ws, bs, wa, ba);
    k1_main<<<NB_K1, 256>>>(prot_node, sub_node, int_index, out);
    k2a_window<<<NB_WIN, 256>>>();
    k3_final<<<1, 1024>>>(prot_node, sub_node, int_index, Wp, bp,
                          sub_out, prot_out, out);
}